// round 17
// baseline (speedup 1.0000x reference)
#include <cuda_runtime.h>

#define N_ 100000
#define E_ 1600000
#define F_ 64
#define CSR_B 148            // co-resident blocks for cooperative CSR build
#define CHUNK 676            // ceil(N_ / CSR_B); 148*676 = 100048 >= N_

// ---------------- static device scratch (no allocation allowed) ----------------
__device__ int    g_is64;            // 1 if edge_index is int64, 0 if int32
__device__ int    g_scancnt;         // cooperative handshake counter
__device__ int    g_work[2];         // work-stealing counters (layer 1, layer 2)
__device__ int    g_deg[N_];
__device__ int    g_off[N_ + 1];
__device__ int    g_cur[N_];
__device__ int    g_bsum[CSR_B];
__device__ int4   g_edge[E_];        // {src, ea.x bits, ea.y bits, 0}
__device__ float  g_xl[N_ * F_];
__device__ float  g_xr[N_ * F_];
__device__ float  g_h [N_ * F_];

// ---------------- packed f32x2 helpers (Blackwell FFMA2) ----------------
__device__ __forceinline__ unsigned long long pack2(float a, float b) {
    unsigned long long r;
    asm("mov.b64 %0, {%1, %2};" : "=l"(r) : "f"(a), "f"(b));
    return r;
}
__device__ __forceinline__ void unpack2(unsigned long long v, float& a, float& b) {
    asm("mov.b64 {%0, %1}, %2;" : "=f"(a), "=f"(b) : "l"(v));
}
__device__ __forceinline__ unsigned long long fma2(unsigned long long a,
                                                   unsigned long long b,
                                                   unsigned long long c) {
    unsigned long long r;
    asm("fma.rn.f32x2 %0, %1, %2, %3;" : "=l"(r) : "l"(a), "l"(b), "l"(c));
    return r;
}

// ---------------- zero + edge_index width detection (merged) ----------------
__global__ void zero_detect_kernel(const int* __restrict__ w) {
    int i = blockIdx.x * blockDim.x + threadIdx.x;
    if (i < N_) g_deg[i] = 0;
    if (i == 0) { g_scancnt = 0; g_work[0] = 0; g_work[1] = 0; }
    if (blockIdx.x == 1) {   // one block does detection in parallel
        __shared__ int nz;
        if (threadIdx.x == 0) nz = 0;
        __syncthreads();
        int acc = 0;
        for (int t = threadIdx.x; t < 4096; t += blockDim.x)
            acc |= w[2 * t + 1];
        if (acc) atomicOr(&nz, 1);
        __syncthreads();
        if (threadIdx.x == 0) g_is64 = (nz == 0) ? 1 : 0;
    }
}

// ---------------- cooperative CSR build: count -> scan -> fill in one kernel ----
__device__ __forceinline__ void grid_handshake(int target) {
    __syncthreads();
    if (threadIdx.x == 0) {
        __threadfence();
        atomicAdd(&g_scancnt, 1);
        while (atomicAdd(&g_scancnt, 0) < target) { }
        __threadfence();
    }
    __syncthreads();
}

__global__ __launch_bounds__(1024) void csr_build_kernel(
    const int* __restrict__ w, const float* __restrict__ ea) {
    const int tid  = threadIdx.x;
    const int bid  = blockIdx.x;
    const int lane = tid & 31;
    const int wid  = tid >> 5;
    const int gidx = bid * 1024 + tid;
    const int gthreads = CSR_B * 1024;
    const int is64 = g_is64;
    __shared__ int ws[32];
    __shared__ int blk_prefix;

    // ---- phase A: count in-degrees ----
    for (int i = gidx; i < E_; i += gthreads) {
        int d = is64 ? w[2 * (E_ + i)] : w[E_ + i];
        atomicAdd(&g_deg[d], 1);
    }
    grid_handshake(CSR_B);

    // ---- phase B: exclusive scan g_deg -> g_off, g_cur ----
    const int idx = bid * CHUNK + tid;          // CHUNK <= 1024
    int v = 0;
    if (tid < CHUNK && idx < N_) v = g_deg[idx];
    int x = v;
    #pragma unroll
    for (int d = 1; d < 32; d <<= 1) {
        int y = __shfl_up_sync(0xffffffffu, x, d);
        if (lane >= d) x += y;
    }
    if (lane == 31) ws[wid] = x;
    __syncthreads();
    if (wid == 0) {
        int t = ws[lane];
        #pragma unroll
        for (int d = 1; d < 32; d <<= 1) {
            int y = __shfl_up_sync(0xffffffffu, t, d);
            if (lane >= d) t += y;
        }
        ws[lane] = t;
    }
    __syncthreads();
    const int block_total = ws[31];

    if (tid == 0) {
        g_bsum[bid] = block_total;
        __threadfence();
        atomicAdd(&g_scancnt, 1);
        while (atomicAdd(&g_scancnt, 0) < 2 * CSR_B) { }
        __threadfence();
        int p = 0;
        for (int b = 0; b < bid; b++) p += *(volatile int*)&g_bsum[b];
        blk_prefix = p;
        if (bid == CSR_B - 1) g_off[N_] = p + block_total;
    }
    __syncthreads();

    const int excl = x - v + ((wid > 0) ? ws[wid - 1] : 0) + blk_prefix;
    if (tid < CHUNK && idx < N_) { g_off[idx] = excl; g_cur[idx] = excl; }
    grid_handshake(3 * CSR_B);

    // ---- phase C: fill edge records ----
    for (int i = gidx; i < E_; i += gthreads) {
        int s = is64 ? w[2 * i]        : w[i];
        int d = is64 ? w[2 * (E_ + i)] : w[E_ + i];
        float2 e = reinterpret_cast<const float2*>(ea)[i];
        int pos = atomicAdd(&g_cur[d], 1);
        g_edge[pos] = make_int4(s, __float_as_int(e.x), __float_as_int(e.y), 0);
    }
}

// ---------------- fused dual GEMM: each thread computes col j of BOTH Wl and Wr ----
__global__ __launch_bounds__(128) void dual_gemm_kernel(
    const float* __restrict__ X,
    const float* __restrict__ Wl, const float* __restrict__ bl,
    const float* __restrict__ Wr, const float* __restrict__ br) {
    __shared__ __align__(16) float xs[16][F_];
    const float* Xp = X ? X : g_h;
    const int tid   = threadIdx.x;          // 0..127
    const int lane  = tid & 31;
    const int warp  = tid >> 5;              // 0..3
    const int col   = warp * 16 + (lane & 15);   // 0..63
    const int khalf = lane >> 4;                  // 0 or 1

    unsigned long long wl2[16], wr2[16];     // 16 k-pairs each = 32 k-values
    #pragma unroll
    for (int t = 0; t < 16; t++) {
        const int k0 = khalf * 32 + 2 * t;
        wl2[t] = pack2(Wl[k0 * 64 + col], Wl[(k0 + 1) * 64 + col]);
        wr2[t] = pack2(Wr[k0 * 64 + col], Wr[(k0 + 1) * 64 + col]);
    }
    const float biasl = bl[col];
    const float biasr = br[col];

    for (int base = blockIdx.x * 16; base < N_; base += gridDim.x * 16) {
        __syncthreads();                     // protect xs reuse
        const float4* srcv = reinterpret_cast<const float4*>(Xp + base * F_);
        float4* dstv = reinterpret_cast<float4*>(xs[0]);
        dstv[tid]       = srcv[tid];         // 256 float4 total, 2 per thread
        dstv[tid + 128] = srcv[tid + 128];
        __syncthreads();

        #pragma unroll 2
        for (int nn = 0; nn < 16; nn++) {
            const ulonglong2* xv =
                reinterpret_cast<const ulonglong2*>(xs[nn]) + khalf * 8;
            unsigned long long aL = pack2(0.f, 0.f), bL = pack2(0.f, 0.f);
            unsigned long long aR = pack2(0.f, 0.f), bR = pack2(0.f, 0.f);
            #pragma unroll
            for (int t = 0; t < 8; t++) {
                ulonglong2 xx = xv[t];       // LDS.128: floats khalf*32+4t..4t+3
                aL = fma2(xx.x, wl2[2 * t],     aL);
                bL = fma2(xx.y, wl2[2 * t + 1], bL);
                aR = fma2(xx.x, wr2[2 * t],     aR);
                bR = fma2(xx.y, wr2[2 * t + 1], bR);
            }
            float a0, a1, b0, b1;
            unpack2(aL, a0, a1); unpack2(bL, b0, b1);
            float rl = (a0 + b0) + (a1 + b1);
            unpack2(aR, a0, a1); unpack2(bR, b0, b1);
            float rr = (a0 + b0) + (a1 + b1);
            rl += __shfl_xor_sync(0xffffffffu, rl, 16);   // combine K-halves
            rr += __shfl_xor_sync(0xffffffffu, rr, 16);
            if (khalf == 0) {
                g_xl[(base + nn) * F_ + col] = biasl + rl;
                g_xr[(base + nn) * F_ + col] = biasr + rr;
            }
        }
    }
}

// ---------------- GATv2 aggregation: 16 lanes per edge, float4 features ----------
// Lane l handles features 4*(l&15)..+3 of edge k+(l>>4): warp = 2 edges/step.
// Work-stealing (592 blocks = 4/SM). Exact softmax without running max
// (logits O(1) by construction). Head reduction: CH/4 lanes per head.
template <int HEADS, int CH, bool FUSE_MLP, int WID>
__global__ __launch_bounds__(256, 4) void gat_aggregate_kernel(
    const float* __restrict__ We,    // (2, 64)
    const float* __restrict__ att,   // (HEADS, CH) flattened == per-feature
    const float* __restrict__ bias,  // (64)
    const float* __restrict__ Wm,    // (64, 8) or nullptr
    const float* __restrict__ bm,    // (8) or nullptr
    float* __restrict__ out)         // (N, 8) or nullptr
{
    const int lane = threadIdx.x & 31;
    const int half = lane >> 4;          // which edge of the pair
    const int ll   = lane & 15;          // feature-group index
    const int fb   = 4 * ll;             // features fb..fb+3
    constexpr int REDL = CH / 4;         // lanes per head (4 or 8), < 16

    // node-independent operands (per 4 features)
    const float4 w04 = *reinterpret_cast<const float4*>(We + fb);
    const float4 w14 = *reinterpret_cast<const float4*>(We + 64 + fb);
    const float4 at4 = *reinterpret_cast<const float4*>(att + fb);
    const float4 bi4 = *reinterpret_cast<const float4*>(bias + fb);

    for (;;) {
        int nbase;
        if (lane == 0) nbase = atomicAdd(&g_work[WID], 4);
        nbase = __shfl_sync(0xffffffffu, nbase, 0);
        if (nbase >= N_) return;
        const int nend = min(nbase + 4, N_);

        for (int d = nbase; d < nend; d++) {
            const float4 xr4 = *reinterpret_cast<const float4*>(g_xr + d * F_ + fb);
            const float4 xl4 = *reinterpret_cast<const float4*>(g_xl + d * F_ + fb);
            const int beg = __ldg(g_off + d);
            const int end = __ldg(g_off + d + 1);

            float  s = 0.f;
            float4 acc = make_float4(0.f, 0.f, 0.f, 0.f);
            float2 easum = make_float2(0.f, 0.f);

            int k = beg;
            // main loop: 2 pairs (4 edges) per iteration
            for (; k + 3 < end; k += 4) {
                const int4 cA = __ldg(g_edge + k + half);
                const int4 cB = __ldg(g_edge + k + 2 + half);
                const float4 xA = *reinterpret_cast<const float4*>(g_xl + cA.x * F_ + fb);
                const float4 xB = *reinterpret_cast<const float4*>(g_xl + cB.x * F_ + fb);

                const float eaxA = __int_as_float(cA.y), eayA = __int_as_float(cA.z);
                const float eaxB = __int_as_float(cB.y), eayB = __int_as_float(cB.z);
                easum.x += eaxA + eaxB;  easum.y += eayA + eayB;

                float a0 = xA.x + xr4.x + eaxA * w04.x + eayA * w14.x;
                float a1 = xA.y + xr4.y + eaxA * w04.y + eayA * w14.y;
                float a2 = xA.z + xr4.z + eaxA * w04.z + eayA * w14.z;
                float a3 = xA.w + xr4.w + eaxA * w04.w + eayA * w14.w;
                float b0 = xB.x + xr4.x + eaxB * w04.x + eayB * w14.x;
                float b1 = xB.y + xr4.y + eaxB * w04.y + eayB * w14.y;
                float b2 = xB.z + xr4.z + eaxB * w04.z + eayB * w14.z;
                float b3 = xB.w + xr4.w + eaxB * w04.w + eayB * w14.w;
                a0 = fmaxf(a0, 0.2f * a0); a1 = fmaxf(a1, 0.2f * a1);
                a2 = fmaxf(a2, 0.2f * a2); a3 = fmaxf(a3, 0.2f * a3);
                b0 = fmaxf(b0, 0.2f * b0); b1 = fmaxf(b1, 0.2f * b1);
                b2 = fmaxf(b2, 0.2f * b2); b3 = fmaxf(b3, 0.2f * b3);
                float zA = a0 * at4.x + a1 * at4.y + a2 * at4.z + a3 * at4.w;
                float zB = b0 * at4.x + b1 * at4.y + b2 * at4.z + b3 * at4.w;
                #pragma unroll
                for (int dl = 1; dl < REDL; dl <<= 1) {   // within-half head reduce
                    zA += __shfl_xor_sync(0xffffffffu, zA, dl);
                    zB += __shfl_xor_sync(0xffffffffu, zB, dl);
                }
                const float pA = __expf(zA);
                const float pB = __expf(zB);
                s += pA + pB;
                acc.x += pA * xA.x + pB * xB.x;
                acc.y += pA * xA.y + pB * xB.y;
                acc.z += pA * xA.z + pB * xB.z;
                acc.w += pA * xA.w + pB * xB.w;
            }
            // pair tail (2 edges)
            if (k + 1 < end) {
                const int4 cA = __ldg(g_edge + k + half);
                const float4 xA = *reinterpret_cast<const float4*>(g_xl + cA.x * F_ + fb);
                const float eaxA = __int_as_float(cA.y), eayA = __int_as_float(cA.z);
                easum.x += eaxA;  easum.y += eayA;
                float a0 = xA.x + xr4.x + eaxA * w04.x + eayA * w14.x;
                float a1 = xA.y + xr4.y + eaxA * w04.y + eayA * w14.y;
                float a2 = xA.z + xr4.z + eaxA * w04.z + eayA * w14.z;
                float a3 = xA.w + xr4.w + eaxA * w04.w + eayA * w14.w;
                a0 = fmaxf(a0, 0.2f * a0); a1 = fmaxf(a1, 0.2f * a1);
                a2 = fmaxf(a2, 0.2f * a2); a3 = fmaxf(a3, 0.2f * a3);
                float zA = a0 * at4.x + a1 * at4.y + a2 * at4.z + a3 * at4.w;
                #pragma unroll
                for (int dl = 1; dl < REDL; dl <<= 1)
                    zA += __shfl_xor_sync(0xffffffffu, zA, dl);
                const float pA = __expf(zA);
                s += pA;
                acc.x += pA * xA.x; acc.y += pA * xA.y;
                acc.z += pA * xA.z; acc.w += pA * xA.w;
                k += 2;
            }
            // single-edge tail: all lanes compute (for shfl convergence),
            // only half 0 accumulates (combine below would double-count).
            if (k < end) {
                const int4 c = __ldg(g_edge + k);
                const float4 xA = *reinterpret_cast<const float4*>(g_xl + c.x * F_ + fb);
                const float eax = __int_as_float(c.y), eay = __int_as_float(c.z);
                float a0 = xA.x + xr4.x + eax * w04.x + eay * w14.x;
                float a1 = xA.y + xr4.y + eax * w04.y + eay * w14.y;
                float a2 = xA.z + xr4.z + eax * w04.z + eay * w14.z;
                float a3 = xA.w + xr4.w + eax * w04.w + eay * w14.w;
                a0 = fmaxf(a0, 0.2f * a0); a1 = fmaxf(a1, 0.2f * a1);
                a2 = fmaxf(a2, 0.2f * a2); a3 = fmaxf(a3, 0.2f * a3);
                float z = a0 * at4.x + a1 * at4.y + a2 * at4.z + a3 * at4.w;
                #pragma unroll
                for (int dl = 1; dl < REDL; dl <<= 1)
                    z += __shfl_xor_sync(0xffffffffu, z, dl);
                if (half == 0) {
                    const float p = __expf(z);
                    s += p;
                    easum.x += eax;     easum.y += eay;
                    acc.x += p * xA.x;  acc.y += p * xA.y;
                    acc.z += p * xA.z;  acc.w += p * xA.w;
                }
            }

            // combine halves (same feature/head layout in both halves)
            s     += __shfl_xor_sync(0xffffffffu, s, 16);
            acc.x += __shfl_xor_sync(0xffffffffu, acc.x, 16);
            acc.y += __shfl_xor_sync(0xffffffffu, acc.y, 16);
            acc.z += __shfl_xor_sync(0xffffffffu, acc.z, 16);
            acc.w += __shfl_xor_sync(0xffffffffu, acc.w, 16);
            easum.x += __shfl_xor_sync(0xffffffffu, easum.x, 16);
            easum.y += __shfl_xor_sync(0xffffffffu, easum.y, 16);

            // self loop (after combine; each lane adds exactly once)
            {
                const float inv_deg = 1.f / fmaxf((float)(end - beg), 1.f);
                const float eax = easum.x * inv_deg;
                const float eay = easum.y * inv_deg;
                float a0 = xl4.x + xr4.x + eax * w04.x + eay * w14.x;
                float a1 = xl4.y + xr4.y + eax * w04.y + eay * w14.y;
                float a2 = xl4.z + xr4.z + eax * w04.z + eay * w14.z;
                float a3 = xl4.w + xr4.w + eax * w04.w + eay * w14.w;
                a0 = fmaxf(a0, 0.2f * a0); a1 = fmaxf(a1, 0.2f * a1);
                a2 = fmaxf(a2, 0.2f * a2); a3 = fmaxf(a3, 0.2f * a3);
                float z = a0 * at4.x + a1 * at4.y + a2 * at4.z + a3 * at4.w;
                #pragma unroll
                for (int dl = 1; dl < REDL; dl <<= 1)
                    z += __shfl_xor_sync(0xffffffffu, z, dl);
                const float p = __expf(z);
                s     += p;
                acc.x += p * xl4.x;  acc.y += p * xl4.y;
                acc.z += p * xl4.z;  acc.w += p * xl4.w;
            }

            const float inv_s = 1.f / s;
            float4 o;
            o.x = fmaxf(acc.x * inv_s + bi4.x, 0.f);   // ReLU after each layer
            o.y = fmaxf(acc.y * inv_s + bi4.y, 0.f);
            o.z = fmaxf(acc.z * inv_s + bi4.z, 0.f);
            o.w = fmaxf(acc.w * inv_s + bi4.w, 0.f);

            if (!FUSE_MLP) {
                if (half == 0)
                    *reinterpret_cast<float4*>(g_h + d * F_ + fb) = o;
            } else {
                // fused head: out[d] = tanh(h @ Wm + bm)
                // lane holds features fb..fb+3 (duplicated across halves);
                // reduce within half (dl<=8) so the duplicate isn't double-counted.
                const float4* W4 = reinterpret_cast<const float4*>(Wm);
                float a[8];
                #pragma unroll
                for (int j = 0; j < 8; j++) a[j] = 0.f;
                const float of[4] = {o.x, o.y, o.z, o.w};
                #pragma unroll
                for (int i = 0; i < 4; i++) {
                    const float4 r0 = W4[(fb + i) * 2];
                    const float4 r1 = W4[(fb + i) * 2 + 1];
                    a[0] += of[i] * r0.x;  a[1] += of[i] * r0.y;
                    a[2] += of[i] * r0.z;  a[3] += of[i] * r0.w;
                    a[4] += of[i] * r1.x;  a[5] += of[i] * r1.y;
                    a[6] += of[i] * r1.z;  a[7] += of[i] * r1.w;
                }
                #pragma unroll
                for (int dl = 8; dl >= 1; dl >>= 1) {
                    #pragma unroll
                    for (int j = 0; j < 8; j++)
                        a[j] += __shfl_xor_sync(0xffffffffu, a[j], dl);
                }
                if (lane == 0) {
                    float4 o0, o1;
                    o0.x = tanhf(a[0] + bm[0]); o0.y = tanhf(a[1] + bm[1]);
                    o0.z = tanhf(a[2] + bm[2]); o0.w = tanhf(a[3] + bm[3]);
                    o1.x = tanhf(a[4] + bm[4]); o1.y = tanhf(a[5] + bm[5]);
                    o1.z = tanhf(a[6] + bm[6]); o1.w = tanhf(a[7] + bm[7]);
                    reinterpret_cast<float4*>(out)[d * 2]     = o0;
                    reinterpret_cast<float4*>(out)[d * 2 + 1] = o1;
                }
            }
        }
    }
}

// ---------------- launch: fork CSR-build branch parallel to gemm1 ----------------
extern "C" void kernel_launch(void* const* d_in, const int* in_sizes, int n_in,
                              void* d_out, int out_size) {
    const float* x    = (const float*)d_in[0];
    const int*   eiw  = (const int*)  d_in[1];   // int32 words; width detected on device
    const float* ea   = (const float*)d_in[2];
    const float* Wl1  = (const float*)d_in[3];
    const float* bl1  = (const float*)d_in[4];
    const float* Wr1  = (const float*)d_in[5];
    const float* br1  = (const float*)d_in[6];
    const float* We1  = (const float*)d_in[7];
    const float* att1 = (const float*)d_in[8];
    const float* b1   = (const float*)d_in[9];
    const float* Wl2  = (const float*)d_in[10];
    const float* bl2  = (const float*)d_in[11];
    const float* Wr2  = (const float*)d_in[12];
    const float* br2  = (const float*)d_in[13];
    const float* We2  = (const float*)d_in[14];
    const float* att2 = (const float*)d_in[15];
    const float* b2   = (const float*)d_in[16];
    const float* Wm   = (const float*)d_in[17];
    const float* bm   = (const float*)d_in[18];
    float* out = (float*)d_out;

    // fork: CSR chain on s1 runs concurrently with gemm1 on the origin stream.
    cudaStream_t s1;
    cudaStreamCreate(&s1);
    cudaEvent_t ev0, ev1;
    cudaEventCreateWithFlags(&ev0, cudaEventDisableTiming);
    cudaEventCreateWithFlags(&ev1, cudaEventDisableTiming);

    cudaEventRecord(ev0, 0);
    cudaStreamWaitEvent(s1, ev0, 0);

    zero_detect_kernel<<<(N_ + 255) / 256, 256, 0, s1>>>(eiw);     // (s1)
    csr_build_kernel  <<<CSR_B, 1024, 0, s1>>>(eiw, ea);           // (s1)
    cudaEventRecord(ev1, s1);

    dual_gemm_kernel  <<<740, 128>>>(x, Wl1, bl1, Wr1, br1);       // origin, concurrent
    cudaStreamWaitEvent(0, ev1, 0);                                // join

    gat_aggregate_kernel<4, 16, false, 0><<<592, 256>>>(           // slot 3 <- profiled
        We1, att1, b1, nullptr, nullptr, nullptr);
    dual_gemm_kernel  <<<740, 128>>>(nullptr, Wl2, bl2, Wr2, br2);
    gat_aggregate_kernel<2, 32, true, 1><<<592, 256>>>(
        We2, att2, b2, Wm, bm, out);
}